// round 4
// baseline (speedup 1.0000x reference)
#include <cuda_runtime.h>
#include <cuda_bf16.h>

// Problem:
//  x   [8192, 32, 32]   z,i,j
//  f0  [32, 16, 16, 16] i,a,b,c
//  f1  [16, 32, 16, 16] a,j,d,e
//  f2  [16, 16, 64, 16] b,d,k,f
//  f3  [16, 16, 16, 64] c,e,f,l
//  bias[64, 64]         k,l
//  out [8192, 64, 64]   z,k,l
//
// Min-FLOP contraction tree (121 GMAC total):
//  G[ij][bd][ce]      = sum_a f0[i,a,b,c] * f1[a,j,d,e]                 (1.1 G)
//  H[ij][(k,f)][(ce)] = F2t[(kf),(bd)] * G_ij[(bd),(ce)]  batched GEMM  (68.7 G)
//  W[(ij,k)][l]       = H[(ij,k),(f,ce)] * F3p[(f,ce),l]  GEMM          (17.2 G)
//  out[z][(kl)]       = x[z,(ij)] * W[(ij),(kl)] + bias   GEMM          (34.4 G)
//
// ij is processed in NCHUNK chunks reusing the G/H scratch (stream-ordered).

#define CHUNK   256
#define NCHUNK  4

// ---------------- scratch (device globals; no dynamic allocation) ------------
__device__ float g_G[(long long)CHUNK * 256 * 256];   //  64 MB [ijc][bd][ce]
__device__ float g_H[(long long)CHUNK * 1024 * 256];  // 256 MB [ijc][(k,f)][(ce)]
__device__ float g_W[1024LL * 4096];                  //  16 MB [(ij)][(k,l)]
__device__ float g_F2t[1024 * 256];                   //   1 MB [(k,f)][(b,d)]
__device__ float g_F3p[4096 * 64];                    //   1 MB [(f,c,e)][l]

// ---------------- prep: permute f2, f3 into GEMM-friendly layouts ------------
__global__ void prep_kernel(const float* __restrict__ f2,
                            const float* __restrict__ f3) {
    int o = blockIdx.x * blockDim.x + threadIdx.x;    // 0 .. 262143
    // F2t[(k*16+f)*256 + (b*16+d)] = f2[(b*16+d)*1024 + (k*16+f)]
    g_F2t[o] = f2[(o & 255) * 1024 + (o >> 8)];
    // F3p[(f*256 + c*16 + e)*64 + l] = f3[((c*16+e)*16 + f)*64 + l]
    int l   = o & 63;
    int fce = o >> 6;
    int f   = fce >> 8;
    int ce  = fce & 255;
    g_F3p[o] = f3[(ce * 16 + f) * 64 + l];
}

// ---------------- stage 1: G[ijc][bd][ce] = sum_a f0 * f1 --------------------
__global__ void __launch_bounds__(256)
pair01_kernel(const float* __restrict__ f0,
              const float* __restrict__ f1,
              int ij_base) {
    __shared__ float s0[4096];   // f0[i][a][b][c]  (a*256 + b*16 + c)
    __shared__ float s1[4096];   // f1[a][j][d][e]  (a*256 + d*16 + e)
    const int t  = threadIdx.x;
    const int ij = ij_base + blockIdx.x;
    const int i  = ij >> 5, j = ij & 31;

    for (int p = t; p < 4096; p += 256) {
        s0[p] = f0[i * 4096 + p];
        int a = p >> 8, de = p & 255;
        s1[p] = f1[a * 8192 + j * 256 + de];
    }
    __syncthreads();

    const int c = t >> 4, e = t & 15;
    float* gout = g_G + (long long)blockIdx.x * 65536;

    for (int b = 0; b < 16; b++) {
        float r0[16];
        #pragma unroll
        for (int a = 0; a < 16; a++) r0[a] = s0[a * 256 + b * 16 + c];
        for (int d = 0; d < 16; d++) {
            float acc = 0.f;
            #pragma unroll
            for (int a = 0; a < 16; a++) acc += r0[a] * s1[a * 256 + d * 16 + e];
            gout[(b * 16 + d) * 256 + t] = acc;   // [bd][ce], coalesced in t
        }
    }
}

// ---------------- generic row-major tiled SGEMM (optionally batched) ---------
// C[M,N] = A[M,K] * B[K,N] (+ bias[N]); lda=K, ldb=N, ldc=N.
template <int BM, int BN, int BK, int TM, int TN, bool ADD_BIAS>
__global__ void __launch_bounds__((BM / TM) * (BN / TN))
sgemm_kernel(const float* __restrict__ A,
             const float* __restrict__ Bp,
             float* __restrict__ C,
             const float* __restrict__ bias,
             int M, int N, int Kd,
             long long strideA, long long strideB, long long strideC) {
    constexpr int THREADS = (BM / TM) * (BN / TN);
    constexpr int A_V4 = BM * BK / 4;
    constexpr int B_V4 = BK * BN / 4;
    static_assert(A_V4 % THREADS == 0, "A load balance");
    static_assert(B_V4 % THREADS == 0, "B load balance");

    const int tid = threadIdx.x;
    const long long bz = blockIdx.z;
    A  += bz * strideA;
    Bp += bz * strideB;
    C  += bz * strideC;

    const int bm = blockIdx.y * BM;
    const int bn = blockIdx.x * BN;

    __shared__ float As[BK][BM + 4];
    __shared__ float Bs[BK][BN];

    const int tx = tid % (BN / TN);
    const int ty = tid / (BN / TN);

    float acc[TM][TN];
    #pragma unroll
    for (int m = 0; m < TM; m++)
        #pragma unroll
        for (int n = 0; n < TN; n++) acc[m][n] = 0.f;

    for (int kt = 0; kt < Kd; kt += BK) {
        // load A tile (transposed into smem)
        #pragma unroll
        for (int q = 0; q < A_V4 / THREADS; q++) {
            int idx  = tid + q * THREADS;
            int row  = idx / (BK / 4);
            int col4 = idx % (BK / 4);
            float4 v = *reinterpret_cast<const float4*>(
                &A[(long long)(bm + row) * Kd + kt + col4 * 4]);
            As[col4 * 4 + 0][row] = v.x;
            As[col4 * 4 + 1][row] = v.y;
            As[col4 * 4 + 2][row] = v.z;
            As[col4 * 4 + 3][row] = v.w;
        }
        // load B tile
        #pragma unroll
        for (int q = 0; q < B_V4 / THREADS; q++) {
            int idx  = tid + q * THREADS;
            int row  = idx / (BN / 4);
            int col4 = idx % (BN / 4);
            *reinterpret_cast<float4*>(&Bs[row][col4 * 4]) =
                *reinterpret_cast<const float4*>(
                    &Bp[(long long)(kt + row) * N + bn + col4 * 4]);
        }
        __syncthreads();

        #pragma unroll
        for (int kk = 0; kk < BK; kk++) {
            float ar[TM], br[TN];
            #pragma unroll
            for (int m = 0; m < TM; m++) ar[m] = As[kk][ty * TM + m];
            #pragma unroll
            for (int n = 0; n < TN; n++) br[n] = Bs[kk][tx * TN + n];
            #pragma unroll
            for (int m = 0; m < TM; m++)
                #pragma unroll
                for (int n = 0; n < TN; n++) acc[m][n] += ar[m] * br[n];
        }
        __syncthreads();
    }

    // store
    #pragma unroll
    for (int m = 0; m < TM; m++) {
        long long row = bm + ty * TM + m;
        #pragma unroll
        for (int n = 0; n < TN; n += 4) {
            int col = bn + tx * TN + n;
            float4 v = make_float4(acc[m][n], acc[m][n + 1],
                                   acc[m][n + 2], acc[m][n + 3]);
            if (ADD_BIAS) {
                float4 bv = *reinterpret_cast<const float4*>(&bias[col]);
                v.x += bv.x; v.y += bv.y; v.z += bv.z; v.w += bv.w;
            }
            *reinterpret_cast<float4*>(&C[row * N + col]) = v;
        }
    }
}

// ---------------- launch ------------------------------------------------------
extern "C" void kernel_launch(void* const* d_in, const int* in_sizes, int n_in,
                              void* d_out, int out_size) {
    const float* x    = (const float*)d_in[0];
    const float* f0   = (const float*)d_in[1];
    const float* f1   = (const float*)d_in[2];
    const float* f2   = (const float*)d_in[3];
    const float* f3   = (const float*)d_in[4];
    const float* bias = (const float*)d_in[5];
    float* out = (float*)d_out;

    float *pG, *pH, *pW, *pF2t, *pF3p;
    cudaGetSymbolAddress((void**)&pG,   g_G);
    cudaGetSymbolAddress((void**)&pH,   g_H);
    cudaGetSymbolAddress((void**)&pW,   g_W);
    cudaGetSymbolAddress((void**)&pF2t, g_F2t);
    cudaGetSymbolAddress((void**)&pF3p, g_F3p);

    // 0) permute f2 -> F2t[(kf),(bd)], f3 -> F3p[(f,ce),l]
    prep_kernel<<<1024, 256>>>(f2, f3);

    for (int c = 0; c < NCHUNK; c++) {
        // 1) G[ijc][bd][ce] for ij in [c*CHUNK, (c+1)*CHUNK)
        pair01_kernel<<<CHUNK, 256>>>(f0, f1, c * CHUNK);

        // 2) batched: H_ijc[1024x256] = F2t[1024x256] * G_ijc[256x256]
        sgemm_kernel<128, 128, 16, 8, 8, false>
            <<<dim3(256 / 128, 1024 / 128, CHUNK), 256>>>(
                pF2t, pG, pH, nullptr,
                /*M=*/1024, /*N=*/256, /*K=*/256,
                /*sA=*/0, /*sB=*/256LL * 256, /*sC=*/1024LL * 256);

        // 3) W rows for this chunk: [CHUNK*64, 64] = H[CHUNK*64, 4096] * F3p
        sgemm_kernel<128, 64, 16, 8, 8, false>
            <<<dim3(1, (CHUNK * 64) / 128, 1), 128>>>(
                pH, pF3p, pW + (long long)c * CHUNK * 64 * 64, nullptr,
                /*M=*/CHUNK * 64, /*N=*/64, /*K=*/4096,
                0, 0, 0);
    }

    // 4) out[8192x4096] = x[8192x1024] * W[1024x4096] + bias
    sgemm_kernel<128, 128, 16, 8, 8, true>
        <<<dim3(4096 / 128, 8192 / 128, 1), 256>>>(
            x, pW, out, bias,
            /*M=*/8192, /*N=*/4096, /*K=*/1024,
            0, 0, 0);
}

// round 7
// speedup vs baseline: 2.3518x; 2.3518x over previous
#include <cuda_runtime.h>
#include <cuda_bf16.h>
#include <cstdint>

// =====================================================================
// Tree (121 GMAC):
//  G[ij][ce][bd]   = sum_a f0[i,a,b,c] f1[a,j,d,e]          (fp32 -> bf16 pair)
//  H[ij][kf][ce]   = F2t[kf,bd] . G_ij[ce,bd]^T             (mma.sync, batched)
//  W[(ij,k)][l]    = H[(ij,k),(f,ce)] . F3T[l,(f,ce)]^T     (mma.sync)
//  out[z][kl]      = x[z,ij] . Wt[kl,ij]^T + bias           (mma.sync)
//
// Operands stored as split-bf16 (hi,lo); each k16 step issues 3 MMAs
// (hi*hi + hi*lo + lo*hi) with fp32 accum => ~1e-5 relative error.
// Legacy sm80 tensor-core path (mma.sync/ldmatrix/cp.async) because the
// harness compiles to PTX target sm_100 (tcgen05 requires sm_100a).
// =====================================================================

#define CHUNK   256
#define NCHUNK  4

typedef __nv_bfloat16 bf16;

// ------------------- scratch (device globals) ------------------------
__device__ __align__(256) bf16 g_F2h[1024 * 256];
__device__ __align__(256) bf16 g_F2l[1024 * 256];
__device__ __align__(256) bf16 g_F3h[64 * 4096];
__device__ __align__(256) bf16 g_F3l[64 * 4096];
__device__ __align__(256) bf16 g_xh[8192 * 1024];
__device__ __align__(256) bf16 g_xl[8192 * 1024];
__device__ __align__(256) bf16 g_Gh[(long long)CHUNK * 256 * 256];
__device__ __align__(256) bf16 g_Gl[(long long)CHUNK * 256 * 256];
__device__ __align__(256) bf16 g_Hh[(long long)CHUNK * 1024 * 256];
__device__ __align__(256) bf16 g_Hl[(long long)CHUNK * 1024 * 256];
__device__ __align__(256) bf16 g_Wh[65536 * 64];
__device__ __align__(256) bf16 g_Wl[65536 * 64];
__device__ __align__(256) bf16 g_Th[4096 * 1024];
__device__ __align__(256) bf16 g_Tl[4096 * 1024];

// ------------------- helpers ------------------------------------------
__device__ __forceinline__ uint32_t smem_u32(const void* p) {
    uint32_t a;
    asm("{ .reg .u64 t; cvta.to.shared.u64 t, %1; cvt.u32.u64 %0, t; }"
        : "=r"(a) : "l"(p));
    return a;
}
__device__ __forceinline__ void cp16(uint32_t s, const void* g) {
    asm volatile("cp.async.cg.shared.global [%0], [%1], 16;" :: "r"(s), "l"(g));
}
__device__ __forceinline__ void cp_commit() {
    asm volatile("cp.async.commit_group;" ::: "memory");
}
__device__ __forceinline__ void cp_wait0() {
    asm volatile("cp.async.wait_group 0;" ::: "memory");
}
__device__ __forceinline__ void ldsm4(uint32_t (&r)[4], uint32_t addr) {
    asm volatile("ldmatrix.sync.aligned.m8n8.x4.shared.b16 {%0,%1,%2,%3}, [%4];"
                 : "=r"(r[0]), "=r"(r[1]), "=r"(r[2]), "=r"(r[3]) : "r"(addr));
}
__device__ __forceinline__ void ldsm2(uint32_t (&r)[2], uint32_t addr) {
    asm volatile("ldmatrix.sync.aligned.m8n8.x2.shared.b16 {%0,%1}, [%2];"
                 : "=r"(r[0]), "=r"(r[1]) : "r"(addr));
}
__device__ __forceinline__ void mma16816(float (&d)[4], const uint32_t (&a)[4],
                                         const uint32_t (&b)[2]) {
    asm volatile(
        "mma.sync.aligned.m16n8k16.row.col.f32.bf16.bf16.f32 "
        "{%0,%1,%2,%3}, {%4,%5,%6,%7}, {%8,%9}, {%0,%1,%2,%3};"
        : "+f"(d[0]), "+f"(d[1]), "+f"(d[2]), "+f"(d[3])
        : "r"(a[0]), "r"(a[1]), "r"(a[2]), "r"(a[3]), "r"(b[0]), "r"(b[1]));
}
__device__ __forceinline__ void split(float v, bf16& h, bf16& l) {
    h = __float2bfloat16(v);
    l = __float2bfloat16(v - __bfloat162float(h));
}

// ------------------- prep: tables + x split ---------------------------
__global__ void prep_tables(const float* __restrict__ f2,
                            const float* __restrict__ f3) {
    int o = blockIdx.x * 256 + threadIdx.x;          // 0 .. 262143
    // F2t[kf][bd] = f2[(bd)*1024 + kf]
    split(f2[(o & 255) * 1024 + (o >> 8)], g_F2h[o], g_F2l[o]);
    // F3T[l][f*256 + c*16 + e] = f3[((c*16+e)*16+f)*64 + l]
    int l = o >> 12, fce = o & 4095, f = fce >> 8, ce = fce & 255;
    split(f3[(ce * 16 + f) * 64 + l], g_F3h[o], g_F3l[o]);
}
__global__ void prep_x(const float* __restrict__ x) {
    int o = blockIdx.x * 256 + threadIdx.x;
    split(x[o], g_xh[o], g_xl[o]);
}

// ------------------- stage 1: G[ijc][ce][bd] --------------------------
__global__ void __launch_bounds__(256)
pair01_kernel(const float* __restrict__ f0, const float* __restrict__ f1,
              int ij_base) {
    __shared__ float s0[4096];   // f0[i]: a*256 + b*16 + c
    __shared__ float s1[4096];   // f1[:,j]: a*256 + d*16 + e
    const int t = threadIdx.x, blk = blockIdx.x;
    const int ij = ij_base + blk, i = ij >> 5, j = ij & 31;

    for (int p = t; p < 4096; p += 256) {
        s0[p] = f0[i * 4096 + p];
        int a = p >> 8, de = p & 255;
        s1[p] = f1[a * 8192 + j * 256 + de];
    }
    __syncthreads();

    const int c = t >> 4, e = t & 15;
    const long long ob = (long long)blk * 65536 + (long long)t * 256;  // row = ce

    for (int b = 0; b < 16; b++) {
        float r0[16];
        #pragma unroll
        for (int a = 0; a < 16; a++) r0[a] = s0[a * 256 + b * 16 + c];
        __align__(16) bf16 hv[16];
        __align__(16) bf16 lv[16];
        #pragma unroll
        for (int d = 0; d < 16; d++) {
            float acc = 0.f;
            #pragma unroll
            for (int a = 0; a < 16; a++) acc += r0[a] * s1[a * 256 + d * 16 + e];
            split(acc, hv[d], lv[d]);
        }
        *reinterpret_cast<uint4*>(&g_Gh[ob + b * 16])     = reinterpret_cast<uint4*>(hv)[0];
        *reinterpret_cast<uint4*>(&g_Gh[ob + b * 16 + 8]) = reinterpret_cast<uint4*>(hv)[1];
        *reinterpret_cast<uint4*>(&g_Gl[ob + b * 16])     = reinterpret_cast<uint4*>(lv)[0];
        *reinterpret_cast<uint4*>(&g_Gl[ob + b * 16 + 8]) = reinterpret_cast<uint4*>(lv)[1];
    }
}

// ------------------- split-bf16 mma.sync GEMM --------------------------
// D[M,N] = A[M,K] * B[N,K]^T ; A,B are (hi,lo) bf16 pairs, K-major rows.
// EPI: 0 -> bf16-pair output, 1 -> fp32 + bias.
template <int BM, int BN, int WM, int WN, int EPI>
__global__ void __launch_bounds__((BM / WM) * (BN / WN) * 32)
gemm_mma(const bf16* __restrict__ Ah, const bf16* __restrict__ Al,
         const bf16* __restrict__ Bh, const bf16* __restrict__ Bl,
         float* __restrict__ Cf, bf16* __restrict__ Ch, bf16* __restrict__ Cl,
         const float* __restrict__ bias,
         int K, int ldC, long long sA, long long sB, long long sC) {
    constexpr int WARPS_M = BM / WM, WARPS_N = BN / WN;
    constexpr int THREADS = WARPS_M * WARPS_N * 32;
    constexpr int MT = WM / 16, NTl = WN / 8;
    constexpr int ROWB = 80;                 // 64B data + 16B pad (bank-safe)
    constexpr int A_SZ = BM * ROWB;
    constexpr int B_SZ = BN * ROWB;
    constexpr int BUFB = 2 * A_SZ + 2 * B_SZ;

    extern __shared__ char sm[];
    const uint32_t sbase = smem_u32(sm);
    const int tid = threadIdx.x, wid = tid >> 5, lane = tid & 31;
    const int warp_m0 = (wid / WARPS_N) * WM;
    const int warp_n0 = (wid % WARPS_N) * WN;

    const long long bz = blockIdx.z;
    Ah += bz * sA;  Al += bz * sA;
    Bh += bz * sB;  Bl += bz * sB;
    const int m0 = blockIdx.y * BM;
    const int n0 = blockIdx.x * BN;

    float acc[MT][NTl][4];
    #pragma unroll
    for (int mi = 0; mi < MT; mi++)
        #pragma unroll
        for (int ni = 0; ni < NTl; ni++)
            #pragma unroll
            for (int c = 0; c < 4; c++) acc[mi][ni][c] = 0.f;

    auto load_chunk = [&](int kt, int buf) {
        const uint32_t sAh = sbase + buf * BUFB;
        const uint32_t sAl = sAh + A_SZ;
        const uint32_t sBh = sAl + A_SZ;
        const uint32_t sBl = sBh + B_SZ;
        #pragma unroll
        for (int p = tid; p < BM * 4; p += THREADS) {
            int row = p >> 2, u = p & 3;
            long long g = (long long)(m0 + row) * K + kt + u * 8;
            uint32_t s = row * ROWB + u * 16;
            cp16(sAh + s, Ah + g);
            cp16(sAl + s, Al + g);
        }
        #pragma unroll
        for (int p = tid; p < BN * 4; p += THREADS) {
            int row = p >> 2, u = p & 3;
            long long g = (long long)(n0 + row) * K + kt + u * 8;
            uint32_t s = row * ROWB + u * 16;
            cp16(sBh + s, Bh + g);
            cp16(sBl + s, Bl + g);
        }
        cp_commit();
    };

    const int nch = K >> 5;   // BK = 32
    load_chunk(0, 0);
    cp_wait0();
    __syncthreads();

    for (int t = 0; t < nch; t++) {
        const int buf = t & 1;
        if (t + 1 < nch) load_chunk((t + 1) * 32, buf ^ 1);

        const uint32_t sAh = sbase + buf * BUFB;
        const uint32_t sAl = sAh + A_SZ;
        const uint32_t sBh = sAl + A_SZ;
        const uint32_t sBl = sBh + B_SZ;

        #pragma unroll
        for (int ks = 0; ks < 2; ks++) {
            uint32_t ah[MT][4], al[MT][4], bh[NTl][2], bl[NTl][2];
            #pragma unroll
            for (int mi = 0; mi < MT; mi++) {
                uint32_t off = (uint32_t)(warp_m0 + mi * 16 + (lane & 15)) * ROWB +
                               ks * 32 + (lane >> 4) * 16;
                ldsm4(ah[mi], sAh + off);
                ldsm4(al[mi], sAl + off);
            }
            #pragma unroll
            for (int ni = 0; ni < NTl; ni++) {
                uint32_t off = (uint32_t)(warp_n0 + ni * 8 + (lane & 7)) * ROWB +
                               ks * 32 + ((lane >> 3) & 1) * 16;
                ldsm2(bh[ni], sBh + off);
                ldsm2(bl[ni], sBl + off);
            }
            #pragma unroll
            for (int mi = 0; mi < MT; mi++)
                #pragma unroll
                for (int ni = 0; ni < NTl; ni++) {
                    mma16816(acc[mi][ni], ah[mi], bh[ni]);
                    mma16816(acc[mi][ni], ah[mi], bl[ni]);
                    mma16816(acc[mi][ni], al[mi], bh[ni]);
                }
        }
        cp_wait0();
        __syncthreads();
    }

    // epilogue: thread holds (r, col),(r, col+1),(r+8, col),(r+8, col+1)
    #pragma unroll
    for (int mi = 0; mi < MT; mi++) {
        #pragma unroll
        for (int ni = 0; ni < NTl; ni++) {
            int r   = m0 + warp_m0 + mi * 16 + (lane >> 2);
            int col = n0 + warp_n0 + ni * 8 + (lane & 3) * 2;
            if (EPI == 0) {
                #pragma unroll
                for (int half = 0; half < 2; half++) {
                    long long off = bz * sC + (long long)(r + half * 8) * ldC + col;
                    bf16 h0, l0, h1, l1;
                    split(acc[mi][ni][half * 2],     h0, l0);
                    split(acc[mi][ni][half * 2 + 1], h1, l1);
                    __nv_bfloat162 hv; hv.x = h0; hv.y = h1;
                    __nv_bfloat162 lv; lv.x = l0; lv.y = l1;
                    *reinterpret_cast<__nv_bfloat162*>(&Ch[off]) = hv;
                    *reinterpret_cast<__nv_bfloat162*>(&Cl[off]) = lv;
                }
            } else {
                float b0 = bias[col], b1 = bias[col + 1];
                #pragma unroll
                for (int half = 0; half < 2; half++) {
                    long long off = (long long)(r + half * 8) * ldC + col;
                    float2 v;
                    v.x = acc[mi][ni][half * 2]     + b0;
                    v.y = acc[mi][ni][half * 2 + 1] + b1;
                    *reinterpret_cast<float2*>(&Cf[off]) = v;
                }
            }
        }
    }
}

// ------------------- W[(ij,k),l] -> Wt[(k,l),ij] ----------------------
__global__ void __launch_bounds__(256)
wtrans_kernel() {
    __shared__ bf16 th[64][65];
    __shared__ bf16 tl[64][65];
    const int k = blockIdx.y;
    const int ijb = blockIdx.x * 64;
    const int tid = threadIdx.x;
    for (int idx = tid; idx < 4096; idx += 256) {
        int r = idx >> 6, l = idx & 63;
        long long g = ((long long)(ijb + r) * 64 + k) * 64 + l;
        th[r][l] = g_Wh[g];
        tl[r][l] = g_Wl[g];
    }
    __syncthreads();
    for (int idx = tid; idx < 4096; idx += 256) {
        int l = idx >> 6, r = idx & 63;
        long long g = ((long long)k * 64 + l) * 1024 + ijb + r;
        g_Th[g] = th[r][l];
        g_Tl[g] = tl[r][l];
    }
}

// ------------------- launch -------------------------------------------
extern "C" void kernel_launch(void* const* d_in, const int* in_sizes, int n_in,
                              void* d_out, int out_size) {
    const float* x    = (const float*)d_in[0];
    const float* f0   = (const float*)d_in[1];
    const float* f1   = (const float*)d_in[2];
    const float* f2   = (const float*)d_in[3];
    const float* f3   = (const float*)d_in[4];
    const float* bias = (const float*)d_in[5];
    float* out = (float*)d_out;

    bf16 *pF2h, *pF2l, *pF3h, *pF3l, *pxh, *pxl;
    bf16 *pGh, *pGl, *pHh, *pHl, *pWh, *pWl, *pTh, *pTl;
    cudaGetSymbolAddress((void**)&pF2h, g_F2h);
    cudaGetSymbolAddress((void**)&pF2l, g_F2l);
    cudaGetSymbolAddress((void**)&pF3h, g_F3h);
    cudaGetSymbolAddress((void**)&pF3l, g_F3l);
    cudaGetSymbolAddress((void**)&pxh,  g_xh);
    cudaGetSymbolAddress((void**)&pxl,  g_xl);
    cudaGetSymbolAddress((void**)&pGh,  g_Gh);
    cudaGetSymbolAddress((void**)&pGl,  g_Gl);
    cudaGetSymbolAddress((void**)&pHh,  g_Hh);
    cudaGetSymbolAddress((void**)&pHl,  g_Hl);
    cudaGetSymbolAddress((void**)&pWh,  g_Wh);
    cudaGetSymbolAddress((void**)&pWl,  g_Wl);
    cudaGetSymbolAddress((void**)&pTh,  g_Th);
    cudaGetSymbolAddress((void**)&pTl,  g_Tl);

    // dynamic smem: 2 buffers of (2*A + 2*B) with 80B rows
    const int SMEM_A = 2 * (2 * 128 * 80 + 2 * 128 * 80);   // 81920
    const int SMEM_B = 2 * (2 * 128 * 80 + 2 * 64 * 80);    // 61440
    cudaFuncSetAttribute((const void*)gemm_mma<128, 128, 64, 32, 0>,
                         cudaFuncAttributeMaxDynamicSharedMemorySize, SMEM_A);
    cudaFuncSetAttribute((const void*)gemm_mma<128, 64, 32, 32, 0>,
                         cudaFuncAttributeMaxDynamicSharedMemorySize, SMEM_B);
    cudaFuncSetAttribute((const void*)gemm_mma<128, 128, 64, 32, 1>,
                         cudaFuncAttributeMaxDynamicSharedMemorySize, SMEM_A);

    prep_tables<<<1024, 256>>>(f2, f3);
    prep_x<<<32768, 256>>>(x);

    for (int c = 0; c < NCHUNK; c++) {
        // stage 1: G[ijc][ce][bd] (bf16 pair)
        pair01_kernel<<<CHUNK, 256>>>(f0, f1, c * CHUNK);

        // stage 2: per-ij H[kf=1024][ce=256] = F2t . G_ij^T   (K=256)
        gemm_mma<128, 128, 64, 32, 0><<<dim3(2, 8, CHUNK), 256, SMEM_A>>>(
            pF2h, pF2l, pGh, pGl,
            nullptr, pHh, pHl, nullptr,
            /*K=*/256, /*ldC=*/256,
            /*sA=*/0, /*sB=*/65536LL, /*sC=*/262144LL);

        // stage 3: W[(ij,k)=16384][l=64] = H . F3T^T          (K=4096)
        gemm_mma<128, 64, 32, 32, 0><<<dim3(1, 128, 1), 256, SMEM_B>>>(
            pHh, pHl, pF3h, pF3l,
            nullptr, pWh + (long long)c * 16384 * 64, pWl + (long long)c * 16384 * 64,
            nullptr,
            /*K=*/4096, /*ldC=*/64,
            0, 0, 0);
    }

    // transpose W -> Wt[(k,l)][ij]
    wtrans_kernel<<<dim3(16, 64), 256>>>();

    // stage 4: out[8192][4096] = x . Wt^T + bias              (K=1024)
    gemm_mma<128, 128, 64, 32, 1><<<dim3(32, 64, 1), 256, SMEM_A>>>(
        pxh, pxl, pTh, pTl,
        out, nullptr, nullptr, bias,
        /*K=*/1024, /*ldC=*/4096,
        0, 0, 0);
}

// round 9
// speedup vs baseline: 2.6617x; 1.1318x over previous
#include <cuda_runtime.h>
#include <cuda_bf16.h>
#include <cstdint>

// =====================================================================
// Tree (121 GMAC):
//  G[ij][ce][bd]   = sum_a f0[i,a,b,c] f1[a,j,d,e]          (fp32 -> bf16 pair)
//  H[ij][kf][ce]   = F2t[kf,bd] . G_ij[ce,bd]^T             (mma.sync, batched)
//  Wp[sp][(ij,k)][l]= H[(ij,k),(f,ce)] . F3T[l,(f,ce)]^T    (mma.sync, K-split x2, fp32)
//  out[z][kl]      = x[z,ij] . Wt[kl,ij]^T + bias           (mma.sync)
//
// Operands stored as split-bf16 (hi,lo); each k16 step issues 3 MMAs
// (hi*hi + hi*lo + lo*hi) with fp32 accum => ~2e-5 relative error.
// sm80 tensor-core path (mma.sync/ldmatrix/cp.async): harness targets PTX
// sm_100 (no tcgen05). Warp tile 64x64, 4 warps/CTA, 2 CTAs/SM.
// =====================================================================

#define CHUNK   256
#define NCHUNK  4

typedef __nv_bfloat16 bf16;

// ------------------- scratch (device globals) ------------------------
__device__ __align__(256) bf16  g_F2h[1024 * 256];
__device__ __align__(256) bf16  g_F2l[1024 * 256];
__device__ __align__(256) bf16  g_F3h[64 * 4096];
__device__ __align__(256) bf16  g_F3l[64 * 4096];
__device__ __align__(256) bf16  g_xh[8192 * 1024];
__device__ __align__(256) bf16  g_xl[8192 * 1024];
__device__ __align__(256) bf16  g_Gh[(long long)CHUNK * 256 * 256];
__device__ __align__(256) bf16  g_Gl[(long long)CHUNK * 256 * 256];
__device__ __align__(256) bf16  g_Hh[(long long)CHUNK * 1024 * 256];
__device__ __align__(256) bf16  g_Hl[(long long)CHUNK * 1024 * 256];
__device__ __align__(256) float g_Wp[2LL * 65536 * 64];      // fp32 K-split partials
__device__ __align__(256) bf16  g_Th[4096 * 1024];
__device__ __align__(256) bf16  g_Tl[4096 * 1024];

// ------------------- helpers ------------------------------------------
__device__ __forceinline__ uint32_t smem_u32(const void* p) {
    uint32_t a;
    asm("{ .reg .u64 t; cvta.to.shared.u64 t, %1; cvt.u32.u64 %0, t; }"
        : "=r"(a) : "l"(p));
    return a;
}
__device__ __forceinline__ void cp16(uint32_t s, const void* g) {
    asm volatile("cp.async.cg.shared.global [%0], [%1], 16;" :: "r"(s), "l"(g));
}
__device__ __forceinline__ void cp_commit() {
    asm volatile("cp.async.commit_group;" ::: "memory");
}
__device__ __forceinline__ void cp_wait0() {
    asm volatile("cp.async.wait_group 0;" ::: "memory");
}
__device__ __forceinline__ void ldsm4(uint32_t& r0, uint32_t& r1,
                                      uint32_t& r2, uint32_t& r3, uint32_t addr) {
    asm volatile("ldmatrix.sync.aligned.m8n8.x4.shared.b16 {%0,%1,%2,%3}, [%4];"
                 : "=r"(r0), "=r"(r1), "=r"(r2), "=r"(r3) : "r"(addr));
}
__device__ __forceinline__ void mma16816(float (&d)[4], const uint32_t (&a)[4],
                                         const uint32_t (&b)[2]) {
    asm volatile(
        "mma.sync.aligned.m16n8k16.row.col.f32.bf16.bf16.f32 "
        "{%0,%1,%2,%3}, {%4,%5,%6,%7}, {%8,%9}, {%0,%1,%2,%3};"
        : "+f"(d[0]), "+f"(d[1]), "+f"(d[2]), "+f"(d[3])
        : "r"(a[0]), "r"(a[1]), "r"(a[2]), "r"(a[3]), "r"(b[0]), "r"(b[1]));
}
__device__ __forceinline__ void split(float v, bf16& h, bf16& l) {
    h = __float2bfloat16(v);
    l = __float2bfloat16(v - __bfloat162float(h));
}

// ------------------- prep: tables + x split ---------------------------
__global__ void prep_tables(const float* __restrict__ f2,
                            const float* __restrict__ f3) {
    int o = blockIdx.x * 256 + threadIdx.x;          // 0 .. 262143
    // F2t[kf][bd] = f2[(bd)*1024 + kf]
    split(f2[(o & 255) * 1024 + (o >> 8)], g_F2h[o], g_F2l[o]);
    // F3T[l][f*256 + c*16 + e] = f3[((c*16+e)*16+f)*64 + l]
    int l = o >> 12, fce = o & 4095, f = fce >> 8, ce = fce & 255;
    split(f3[(ce * 16 + f) * 64 + l], g_F3h[o], g_F3l[o]);
}
__global__ void prep_x(const float* __restrict__ x) {
    int o = blockIdx.x * 256 + threadIdx.x;
    split(x[o], g_xh[o], g_xl[o]);
}

// ------------------- stage 1: G[ijc][ce][bd] --------------------------
__global__ void __launch_bounds__(256)
pair01_kernel(const float* __restrict__ f0, const float* __restrict__ f1,
              int ij_base) {
    __shared__ float s0[4096];   // f0[i]: a*256 + b*16 + c
    __shared__ float s1[4096];   // f1[:,j]: a*256 + d*16 + e
    const int t = threadIdx.x, blk = blockIdx.x;
    const int ij = ij_base + blk, i = ij >> 5, j = ij & 31;

    for (int p = t; p < 4096; p += 256) {
        s0[p] = f0[i * 4096 + p];
        int a = p >> 8, de = p & 255;
        s1[p] = f1[a * 8192 + j * 256 + de];
    }
    __syncthreads();

    const int c = t >> 4, e = t & 15;
    const long long ob = (long long)blk * 65536 + (long long)t * 256;  // row = ce

    for (int b = 0; b < 16; b++) {
        float r0[16];
        #pragma unroll
        for (int a = 0; a < 16; a++) r0[a] = s0[a * 256 + b * 16 + c];
        __align__(16) bf16 hv[16];
        __align__(16) bf16 lv[16];
        #pragma unroll
        for (int d = 0; d < 16; d++) {
            float acc = 0.f;
            #pragma unroll
            for (int a = 0; a < 16; a++) acc += r0[a] * s1[a * 256 + d * 16 + e];
            split(acc, hv[d], lv[d]);
        }
        *reinterpret_cast<uint4*>(&g_Gh[ob + b * 16])     = reinterpret_cast<uint4*>(hv)[0];
        *reinterpret_cast<uint4*>(&g_Gh[ob + b * 16 + 8]) = reinterpret_cast<uint4*>(hv)[1];
        *reinterpret_cast<uint4*>(&g_Gl[ob + b * 16])     = reinterpret_cast<uint4*>(lv)[0];
        *reinterpret_cast<uint4*>(&g_Gl[ob + b * 16 + 8]) = reinterpret_cast<uint4*>(lv)[1];
    }
}

// ------------------- split-bf16 mma.sync GEMM --------------------------
// D[M,N] = A[M,K_red] * B[N,K_red]^T ; A,B (hi,lo) bf16 pairs, K-major rows
// with leading dims lda/ldb. z-dim: A += z*sA, B += z*sB, C += z*sC.
// EPI: 0 -> bf16-pair out; 1 -> fp32 + bias; 2 -> fp32 plain (partials).
template <int BM, int BN, int WM, int WN, int EPI>
__global__ void __launch_bounds__((BM / WM) * (BN / WN) * 32)
gemm_mma(const bf16* __restrict__ Ah, const bf16* __restrict__ Al,
         const bf16* __restrict__ Bh, const bf16* __restrict__ Bl,
         float* __restrict__ Cf, bf16* __restrict__ Ch, bf16* __restrict__ Cl,
         const float* __restrict__ bias,
         int K, int lda, int ldb, int ldC,
         long long sA, long long sB, long long sC) {
    constexpr int WARPS_M = BM / WM, WARPS_N = BN / WN;
    constexpr int THREADS = WARPS_M * WARPS_N * 32;
    constexpr int MT = WM / 16, NT = WN / 8;
    static_assert(NT % 2 == 0, "NT even for paired ldsm4");
    constexpr int ROWB = 80;                 // 64B data + 16B pad (bank-safe)
    constexpr int A_SZ = BM * ROWB;
    constexpr int B_SZ = BN * ROWB;
    constexpr int BUFB = 2 * A_SZ + 2 * B_SZ;

    extern __shared__ char sm[];
    const uint32_t sbase = smem_u32(sm);
    const int tid = threadIdx.x, wid = tid >> 5, lane = tid & 31;
    const int warp_m0 = (wid / WARPS_N) * WM;
    const int warp_n0 = (wid % WARPS_N) * WN;

    const long long bz = blockIdx.z;
    Ah += bz * sA;  Al += bz * sA;
    Bh += bz * sB;  Bl += bz * sB;
    const int m0 = blockIdx.y * BM;
    const int n0 = blockIdx.x * BN;

    float acc[MT][NT][4];
    #pragma unroll
    for (int mi = 0; mi < MT; mi++)
        #pragma unroll
        for (int ni = 0; ni < NT; ni++)
            #pragma unroll
            for (int c = 0; c < 4; c++) acc[mi][ni][c] = 0.f;

    auto load_chunk = [&](int kt, int buf) {
        const uint32_t sAh = sbase + buf * BUFB;
        const uint32_t sAl = sAh + A_SZ;
        const uint32_t sBh = sAl + A_SZ;
        const uint32_t sBl = sBh + B_SZ;
        #pragma unroll
        for (int p = tid; p < BM * 4; p += THREADS) {
            int row = p >> 2, u = p & 3;
            long long g = (long long)(m0 + row) * lda + kt + u * 8;
            uint32_t s = row * ROWB + u * 16;
            cp16(sAh + s, Ah + g);
            cp16(sAl + s, Al + g);
        }
        #pragma unroll
        for (int p = tid; p < BN * 4; p += THREADS) {
            int row = p >> 2, u = p & 3;
            long long g = (long long)(n0 + row) * ldb + kt + u * 8;
            uint32_t s = row * ROWB + u * 16;
            cp16(sBh + s, Bh + g);
            cp16(sBl + s, Bl + g);
        }
        cp_commit();
    };

    const int nch = K >> 5;   // BK = 32
    load_chunk(0, 0);
    cp_wait0();
    __syncthreads();

    for (int t = 0; t < nch; t++) {
        const int buf = t & 1;
        if (t + 1 < nch) load_chunk((t + 1) * 32, buf ^ 1);

        const uint32_t sAh = sbase + buf * BUFB;
        const uint32_t sAl = sAh + A_SZ;
        const uint32_t sBh = sAl + A_SZ;
        const uint32_t sBl = sBh + B_SZ;

        #pragma unroll
        for (int ks = 0; ks < 2; ks++) {
            uint32_t ah[MT][4], al[MT][4], bh[NT][2], bl[NT][2];
            #pragma unroll
            for (int mi = 0; mi < MT; mi++) {
                uint32_t off = (uint32_t)(warp_m0 + mi * 16 + (lane & 15)) * ROWB +
                               ks * 32 + (lane >> 4) * 16;
                ldsm4(ah[mi][0], ah[mi][1], ah[mi][2], ah[mi][3], sAh + off);
                ldsm4(al[mi][0], al[mi][1], al[mi][2], al[mi][3], sAl + off);
            }
            #pragma unroll
            for (int ni = 0; ni < NT; ni += 2) {
                uint32_t off = (uint32_t)(warp_n0 + ni * 8 + ((lane >> 4) << 3) +
                                          (lane & 7)) * ROWB +
                               ks * 32 + ((lane >> 3) & 1) * 16;
                ldsm4(bh[ni][0], bh[ni][1], bh[ni + 1][0], bh[ni + 1][1], sBh + off);
                ldsm4(bl[ni][0], bl[ni][1], bl[ni + 1][0], bl[ni + 1][1], sBl + off);
            }
            #pragma unroll
            for (int mi = 0; mi < MT; mi++)
                #pragma unroll
                for (int ni = 0; ni < NT; ni++) {
                    mma16816(acc[mi][ni], ah[mi], bh[ni]);
                    mma16816(acc[mi][ni], ah[mi], bl[ni]);
                    mma16816(acc[mi][ni], al[mi], bh[ni]);
                }
        }
        cp_wait0();
        __syncthreads();
    }

    // epilogue: thread holds (r, col),(r, col+1),(r+8, col),(r+8, col+1)
    #pragma unroll
    for (int mi = 0; mi < MT; mi++) {
        #pragma unroll
        for (int ni = 0; ni < NT; ni++) {
            int r   = m0 + warp_m0 + mi * 16 + (lane >> 2);
            int col = n0 + warp_n0 + ni * 8 + (lane & 3) * 2;
            if (EPI == 0) {
                #pragma unroll
                for (int half = 0; half < 2; half++) {
                    long long off = bz * sC + (long long)(r + half * 8) * ldC + col;
                    bf16 h0, l0, h1, l1;
                    split(acc[mi][ni][half * 2],     h0, l0);
                    split(acc[mi][ni][half * 2 + 1], h1, l1);
                    __nv_bfloat162 hv; hv.x = h0; hv.y = h1;
                    __nv_bfloat162 lv; lv.x = l0; lv.y = l1;
                    *reinterpret_cast<__nv_bfloat162*>(&Ch[off]) = hv;
                    *reinterpret_cast<__nv_bfloat162*>(&Cl[off]) = lv;
                }
            } else if (EPI == 1) {
                float b0 = bias[col], b1 = bias[col + 1];
                #pragma unroll
                for (int half = 0; half < 2; half++) {
                    long long off = (long long)(r + half * 8) * ldC + col;
                    float2 v;
                    v.x = acc[mi][ni][half * 2]     + b0;
                    v.y = acc[mi][ni][half * 2 + 1] + b1;
                    *reinterpret_cast<float2*>(&Cf[off]) = v;
                }
            } else {
                #pragma unroll
                for (int half = 0; half < 2; half++) {
                    long long off = bz * sC + (long long)(r + half * 8) * ldC + col;
                    float2 v;
                    v.x = acc[mi][ni][half * 2];
                    v.y = acc[mi][ni][half * 2 + 1];
                    *reinterpret_cast<float2*>(&Cf[off]) = v;
                }
            }
        }
    }
}

// ----------- Wp partials -> sum -> Wt[(k,l)][ij] (split bf16) ---------
__global__ void __launch_bounds__(256)
wtrans_kernel() {
    __shared__ bf16 th[64][65];
    __shared__ bf16 tl[64][65];
    const int k = blockIdx.y;
    const int ijb = blockIdx.x * 64;
    const int tid = threadIdx.x;
    for (int idx = tid; idx < 4096; idx += 256) {
        int r = idx >> 6, l = idx & 63;
        long long g = ((long long)(ijb + r) * 64 + k) * 64 + l;
        float v = g_Wp[g] + g_Wp[g + 65536LL * 64];
        split(v, th[r][l], tl[r][l]);
    }
    __syncthreads();
    for (int idx = tid; idx < 4096; idx += 256) {
        int l = idx >> 6, r = idx & 63;
        long long g = ((long long)k * 64 + l) * 1024 + ijb + r;
        g_Th[g] = th[r][l];
        g_Tl[g] = tl[r][l];
    }
}

// ------------------- launch -------------------------------------------
extern "C" void kernel_launch(void* const* d_in, const int* in_sizes, int n_in,
                              void* d_out, int out_size) {
    const float* x    = (const float*)d_in[0];
    const float* f0   = (const float*)d_in[1];
    const float* f1   = (const float*)d_in[2];
    const float* f2   = (const float*)d_in[3];
    const float* f3   = (const float*)d_in[4];
    const float* bias = (const float*)d_in[5];
    float* out = (float*)d_out;

    bf16 *pF2h, *pF2l, *pF3h, *pF3l, *pxh, *pxl;
    bf16 *pGh, *pGl, *pHh, *pHl, *pTh, *pTl;
    float* pWp;
    cudaGetSymbolAddress((void**)&pF2h, g_F2h);
    cudaGetSymbolAddress((void**)&pF2l, g_F2l);
    cudaGetSymbolAddress((void**)&pF3h, g_F3h);
    cudaGetSymbolAddress((void**)&pF3l, g_F3l);
    cudaGetSymbolAddress((void**)&pxh,  g_xh);
    cudaGetSymbolAddress((void**)&pxl,  g_xl);
    cudaGetSymbolAddress((void**)&pGh,  g_Gh);
    cudaGetSymbolAddress((void**)&pGl,  g_Gl);
    cudaGetSymbolAddress((void**)&pHh,  g_Hh);
    cudaGetSymbolAddress((void**)&pHl,  g_Hl);
    cudaGetSymbolAddress((void**)&pWp,  g_Wp);
    cudaGetSymbolAddress((void**)&pTh,  g_Th);
    cudaGetSymbolAddress((void**)&pTl,  g_Tl);

    // dynamic smem: 2 buffers of (2*A + 2*B) with 80B rows
    const int SMEM_A = 2 * (2 * 128 * 80 + 2 * 128 * 80);   // 81920
    const int SMEM_C = 2 * (2 * 128 * 80 + 2 * 64 * 80);    // 61440
    cudaFuncSetAttribute((const void*)gemm_mma<128, 128, 64, 64, 0>,
                         cudaFuncAttributeMaxDynamicSharedMemorySize, SMEM_A);
    cudaFuncSetAttribute((const void*)gemm_mma<128, 64, 64, 32, 2>,
                         cudaFuncAttributeMaxDynamicSharedMemorySize, SMEM_C);
    cudaFuncSetAttribute((const void*)gemm_mma<128, 128, 64, 64, 1>,
                         cudaFuncAttributeMaxDynamicSharedMemorySize, SMEM_A);

    prep_tables<<<1024, 256>>>(f2, f3);
    prep_x<<<32768, 256>>>(x);

    for (int c = 0; c < NCHUNK; c++) {
        // stage 1: G[ijc][ce][bd] (bf16 pair)
        pair01_kernel<<<CHUNK, 256>>>(f0, f1, c * CHUNK);

        // stage 2: per-ij H[kf=1024][ce=256] = F2t . G_ij^T   (K=256)
        gemm_mma<128, 128, 64, 64, 0><<<dim3(2, 8, CHUNK), 128, SMEM_A>>>(
            pF2h, pF2l, pGh, pGl,
            nullptr, pHh, pHl, nullptr,
            /*K=*/256, /*lda=*/256, /*ldb=*/256, /*ldC=*/256,
            /*sA=*/0, /*sB=*/65536LL, /*sC=*/262144LL);

        // stage 3: Wp[sp][(ij,k)=16384][l=64] = H . F3T^T  (K-split 2 x 2048)
        gemm_mma<128, 64, 64, 32, 2><<<dim3(1, 128, 2), 128, SMEM_C>>>(
            pHh, pHl, pF3h, pF3l,
            pWp + (long long)c * 16384 * 64, nullptr, nullptr, nullptr,
            /*K=*/2048, /*lda=*/4096, /*ldb=*/4096, /*ldC=*/64,
            /*sA=*/2048, /*sB=*/2048, /*sC=*/65536LL * 64);
    }

    // sum partials + transpose -> Wt[(k,l)][ij] (split bf16)
    wtrans_kernel<<<dim3(16, 64), 256>>>();

    // stage 4: out[8192][4096] = x . Wt^T + bias              (K=1024)
    gemm_mma<128, 128, 64, 64, 1><<<dim3(32, 64, 1), 128, SMEM_A>>>(
        pxh, pxl, pTh, pTl,
        out, nullptr, nullptr, bias,
        /*K=*/1024, /*lda=*/1024, /*ldb=*/1024, /*ldC=*/4096,
        0, 0, 0);
}

// round 11
// speedup vs baseline: 4.2561x; 1.5990x over previous
#include <cuda_runtime.h>
#include <cuda_fp16.h>
#include <cstdint>

// =====================================================================
// Tree (121 GMAC):
//  G[ij][ce][bd]    = sum_a f0[i,a,b,c] f1[a,j,d,e]       (fp32 -> fp16 single)
//  H[ij][kf][ce]    = (F2h+F2l)[kf,bd] . G[ce,bd]^T       (2-MMA, batched)
//  Wt_pre[l][(ij,k)]= (F3h+F3l)[l,(f,ce)] . H[(ij,k),(f,ce)]^T  (2-MMA)
//  out[z][kl]       = (xh+xl)[z,ij] . Wt[kl,ij]^T + bias  (2-MMA)
//
// 2-MMA scheme: split operand A into exact fp16 (hi,lo) pair (error 2^-22),
// keep B as single fp16 (error 2^-11 ~ 2.8e-4 RMS per stage). Total rel_err
// ~ 5e-4 < 1e-3. Issued tensor FLOPs: 481 GFLOP at ~300 TF/s (the measured
// legacy mma.sync ceiling on this chip; harness PTX target sm_100 => no
// tcgen05).
// =====================================================================

typedef __half fp16;

// ------------------- scratch (device globals) ------------------------
__device__ __align__(256) fp16  g_F2h[1024 * 256];           // pair
__device__ __align__(256) fp16  g_F2l[1024 * 256];
__device__ __align__(256) fp16  g_F3h[64 * 4096];            // pair
__device__ __align__(256) fp16  g_F3l[64 * 4096];
__device__ __align__(256) fp16  g_xh[8192 * 1024];           // pair
__device__ __align__(256) fp16  g_xl[8192 * 1024];
__device__ __align__(256) fp16  g_G[1024LL * 256 * 256];     // single, 128 MB
__device__ __align__(256) fp16  g_H[1024LL * 1024 * 256];    // single, 512 MB
__device__ __align__(256) float g_Wpre[64LL * 65536];        // fp32, 16 MB
__device__ __align__(256) fp16  g_Wt[4096 * 1024];           // single, 8 MB

// ------------------- helpers ------------------------------------------
__device__ __forceinline__ uint32_t smem_u32(const void* p) {
    uint32_t a;
    asm("{ .reg .u64 t; cvta.to.shared.u64 t, %1; cvt.u32.u64 %0, t; }"
        : "=r"(a) : "l"(p));
    return a;
}
__device__ __forceinline__ void cp16(uint32_t s, const void* g) {
    asm volatile("cp.async.cg.shared.global [%0], [%1], 16;" :: "r"(s), "l"(g));
}
__device__ __forceinline__ void cp_commit() {
    asm volatile("cp.async.commit_group;" ::: "memory");
}
__device__ __forceinline__ void cp_wait0() {
    asm volatile("cp.async.wait_group 0;" ::: "memory");
}
__device__ __forceinline__ void ldsm4(uint32_t& r0, uint32_t& r1,
                                      uint32_t& r2, uint32_t& r3, uint32_t addr) {
    asm volatile("ldmatrix.sync.aligned.m8n8.x4.shared.b16 {%0,%1,%2,%3}, [%4];"
                 : "=r"(r0), "=r"(r1), "=r"(r2), "=r"(r3) : "r"(addr));
}
__device__ __forceinline__ void mma16816(float (&d)[4], const uint32_t (&a)[4],
                                         const uint32_t (&b)[2]) {
    asm volatile(
        "mma.sync.aligned.m16n8k16.row.col.f32.f16.f16.f32 "
        "{%0,%1,%2,%3}, {%4,%5,%6,%7}, {%8,%9}, {%0,%1,%2,%3};"
        : "+f"(d[0]), "+f"(d[1]), "+f"(d[2]), "+f"(d[3])
        : "r"(a[0]), "r"(a[1]), "r"(a[2]), "r"(a[3]), "r"(b[0]), "r"(b[1]));
}
__device__ __forceinline__ void split(float v, fp16& h, fp16& l) {
    h = __float2half(v);
    l = __float2half(v - __half2float(h));
}

// ------------------- prep: tables + x split ---------------------------
__global__ void prep_tables(const float* __restrict__ f2,
                            const float* __restrict__ f3) {
    int o = blockIdx.x * 256 + threadIdx.x;          // 0 .. 262143
    // F2t[kf][bd] = f2[(bd)*1024 + kf]   (exact fp16 pair)
    split(f2[(o & 255) * 1024 + (o >> 8)], g_F2h[o], g_F2l[o]);
    // F3T[l][f*256 + c*16 + e] = f3[((c*16+e)*16+f)*64 + l]   (exact pair)
    int l = o >> 12, fce = o & 4095, f = fce >> 8, ce = fce & 255;
    split(f3[(ce * 16 + f) * 64 + l], g_F3h[o], g_F3l[o]);
}
__global__ void prep_x(const float* __restrict__ x) {
    int o = blockIdx.x * 256 + threadIdx.x;
    split(x[o], g_xh[o], g_xl[o]);
}

// ------------------- stage 1: G[ij][ce][bd] fp16 single ----------------
__global__ void __launch_bounds__(256)
pair01_kernel(const float* __restrict__ f0, const float* __restrict__ f1) {
    __shared__ float s0[4096];   // f0[i]: a*256 + b*16 + c
    __shared__ float s1[4096];   // f1[:,j]: a*256 + d*16 + e
    const int t = threadIdx.x, ij = blockIdx.x;
    const int i = ij >> 5, j = ij & 31;

    for (int p = t; p < 4096; p += 256) {
        s0[p] = f0[i * 4096 + p];
        int a = p >> 8, de = p & 255;
        s1[p] = f1[a * 8192 + j * 256 + de];
    }
    __syncthreads();

    const int c = t >> 4, e = t & 15;
    const long long ob = (long long)ij * 65536 + (long long)t * 256;  // row = ce

    for (int b = 0; b < 16; b++) {
        float r0[16];
        #pragma unroll
        for (int a = 0; a < 16; a++) r0[a] = s0[a * 256 + b * 16 + c];
        __align__(16) fp16 hv[16];
        #pragma unroll
        for (int d = 0; d < 16; d++) {
            float acc = 0.f;
            #pragma unroll
            for (int a = 0; a < 16; a++) acc += r0[a] * s1[a * 256 + d * 16 + e];
            hv[d] = __float2half(acc);
        }
        *reinterpret_cast<uint4*>(&g_G[ob + b * 16])     = reinterpret_cast<uint4*>(hv)[0];
        *reinterpret_cast<uint4*>(&g_G[ob + b * 16 + 8]) = reinterpret_cast<uint4*>(hv)[1];
    }
}

// ------------------- 2-MMA fp16 GEMM -----------------------------------
// D[M,N] = (Ah+Al)[M,K] * Bs[N,K]^T ; all K-major rows, lda/ldb leads.
// z-dim: Bs += z*sB, C += z*sC  (A has no batch).
// EPI: 0 -> fp16 single out; 1 -> fp32 + bias; 2 -> fp32 plain.
template <int BM, int BN, int WM, int WN, int EPI>
__global__ void __launch_bounds__((BM / WM) * (BN / WN) * 32)
gemm_mma(const fp16* __restrict__ Ah, const fp16* __restrict__ Al,
         const fp16* __restrict__ Bs,
         float* __restrict__ Cf, fp16* __restrict__ Ch,
         const float* __restrict__ bias,
         int K, int lda, int ldb, int ldC,
         long long sB, long long sC) {
    constexpr int WARPS_M = BM / WM, WARPS_N = BN / WN;
    constexpr int THREADS = WARPS_M * WARPS_N * 32;
    constexpr int MT = WM / 16, NT = WN / 8;
    static_assert(NT % 2 == 0, "NT even for paired ldsm4");
    constexpr int ROWB = 80;                 // 64B data + 16B pad (bank-safe)
    constexpr int A_SZ = BM * ROWB;
    constexpr int B_SZ = BN * ROWB;
    constexpr int BUFB = 2 * A_SZ + B_SZ;    // A pair + B single

    extern __shared__ char sm[];
    const uint32_t sbase = smem_u32(sm);
    const int tid = threadIdx.x, wid = tid >> 5, lane = tid & 31;
    const int warp_m0 = (wid / WARPS_N) * WM;
    const int warp_n0 = (wid % WARPS_N) * WN;

    const long long bz = blockIdx.z;
    Bs += bz * sB;
    const int m0 = blockIdx.y * BM;
    const int n0 = blockIdx.x * BN;

    float acc[MT][NT][4];
    #pragma unroll
    for (int mi = 0; mi < MT; mi++)
        #pragma unroll
        for (int ni = 0; ni < NT; ni++)
            #pragma unroll
            for (int c = 0; c < 4; c++) acc[mi][ni][c] = 0.f;

    auto load_chunk = [&](int kt, int buf) {
        const uint32_t sAh = sbase + buf * BUFB;
        const uint32_t sAl = sAh + A_SZ;
        const uint32_t sBb = sAl + A_SZ;
        #pragma unroll
        for (int p = tid; p < BM * 4; p += THREADS) {
            int row = p >> 2, u = p & 3;
            long long g = (long long)(m0 + row) * lda + kt + u * 8;
            uint32_t s = row * ROWB + u * 16;
            cp16(sAh + s, Ah + g);
            cp16(sAl + s, Al + g);
        }
        #pragma unroll
        for (int p = tid; p < BN * 4; p += THREADS) {
            int row = p >> 2, u = p & 3;
            long long g = (long long)(n0 + row) * ldb + kt + u * 8;
            cp16(sBb + row * ROWB + u * 16, Bs + g);
        }
        cp_commit();
    };

    const int nch = K >> 5;   // BK = 32
    load_chunk(0, 0);
    cp_wait0();
    __syncthreads();

    for (int t = 0; t < nch; t++) {
        const int buf = t & 1;
        if (t + 1 < nch) load_chunk((t + 1) * 32, buf ^ 1);

        const uint32_t sAh = sbase + buf * BUFB;
        const uint32_t sAl = sAh + A_SZ;
        const uint32_t sBb = sAl + A_SZ;

        #pragma unroll
        for (int ks = 0; ks < 2; ks++) {
            uint32_t ah[MT][4], al[MT][4], bq[NT][2];
            #pragma unroll
            for (int mi = 0; mi < MT; mi++) {
                uint32_t off = (uint32_t)(warp_m0 + mi * 16 + (lane & 15)) * ROWB +
                               ks * 32 + (lane >> 4) * 16;
                ldsm4(ah[mi][0], ah[mi][1], ah[mi][2], ah[mi][3], sAh + off);
                ldsm4(al[mi][0], al[mi][1], al[mi][2], al[mi][3], sAl + off);
            }
            #pragma unroll
            for (int ni = 0; ni < NT; ni += 2) {
                uint32_t off = (uint32_t)(warp_n0 + ni * 8 + ((lane >> 4) << 3) +
                                          (lane & 7)) * ROWB +
                               ks * 32 + ((lane >> 3) & 1) * 16;
                ldsm4(bq[ni][0], bq[ni][1], bq[ni + 1][0], bq[ni + 1][1], sBb + off);
            }
            #pragma unroll
            for (int mi = 0; mi < MT; mi++)
                #pragma unroll
                for (int ni = 0; ni < NT; ni++) {
                    mma16816(acc[mi][ni], ah[mi], bq[ni]);
                    mma16816(acc[mi][ni], al[mi], bq[ni]);
                }
        }
        cp_wait0();
        __syncthreads();
    }

    // epilogue: thread holds (r, col),(r, col+1),(r+8, col),(r+8, col+1)
    #pragma unroll
    for (int mi = 0; mi < MT; mi++) {
        #pragma unroll
        for (int ni = 0; ni < NT; ni++) {
            int r   = m0 + warp_m0 + mi * 16 + (lane >> 2);
            int col = n0 + warp_n0 + ni * 8 + (lane & 3) * 2;
            if (EPI == 0) {
                #pragma unroll
                for (int half_ = 0; half_ < 2; half_++) {
                    long long off = bz * sC + (long long)(r + half_ * 8) * ldC + col;
                    __half2 hv;
                    hv.x = __float2half(acc[mi][ni][half_ * 2]);
                    hv.y = __float2half(acc[mi][ni][half_ * 2 + 1]);
                    *reinterpret_cast<__half2*>(&Ch[off]) = hv;
                }
            } else if (EPI == 1) {
                float b0 = bias[col], b1 = bias[col + 1];
                #pragma unroll
                for (int half_ = 0; half_ < 2; half_++) {
                    long long off = (long long)(r + half_ * 8) * ldC + col;
                    float2 v;
                    v.x = acc[mi][ni][half_ * 2]     + b0;
                    v.y = acc[mi][ni][half_ * 2 + 1] + b1;
                    *reinterpret_cast<float2*>(&Cf[off]) = v;
                }
            } else {
                #pragma unroll
                for (int half_ = 0; half_ < 2; half_++) {
                    long long off = (long long)(r + half_ * 8) * ldC + col;
                    float2 v;
                    v.x = acc[mi][ni][half_ * 2];
                    v.y = acc[mi][ni][half_ * 2 + 1];
                    *reinterpret_cast<float2*>(&Cf[off]) = v;
                }
            }
        }
    }
}

// -------- Wpre[l][(ij,k)] fp32 -> Wt[(k*64+l)][ij] fp16 single ---------
__global__ void __launch_bounds__(256)
wtrans_kernel() {
    const int kl = blockIdx.x;           // 0..4095
    const int k = kl >> 6, l = kl & 63;
    const int t = threadIdx.x;
    #pragma unroll
    for (int q = 0; q < 4; q++) {
        int ij = t + q * 256;
        float v = g_Wpre[(long long)l * 65536 + ij * 64 + k];
        g_Wt[(long long)kl * 1024 + ij] = __float2half(v);
    }
}

// ------------------- launch -------------------------------------------
extern "C" void kernel_launch(void* const* d_in, const int* in_sizes, int n_in,
                              void* d_out, int out_size) {
    const float* x    = (const float*)d_in[0];
    const float* f0   = (const float*)d_in[1];
    const float* f1   = (const float*)d_in[2];
    const float* f2   = (const float*)d_in[3];
    const float* f3   = (const float*)d_in[4];
    const float* bias = (const float*)d_in[5];
    float* out = (float*)d_out;

    fp16 *pF2h, *pF2l, *pF3h, *pF3l, *pxh, *pxl, *pG, *pH, *pWt;
    float* pWpre;
    cudaGetSymbolAddress((void**)&pF2h, g_F2h);
    cudaGetSymbolAddress((void**)&pF2l, g_F2l);
    cudaGetSymbolAddress((void**)&pF3h, g_F3h);
    cudaGetSymbolAddress((void**)&pF3l, g_F3l);
    cudaGetSymbolAddress((void**)&pxh,  g_xh);
    cudaGetSymbolAddress((void**)&pxl,  g_xl);
    cudaGetSymbolAddress((void**)&pG,   g_G);
    cudaGetSymbolAddress((void**)&pH,   g_H);
    cudaGetSymbolAddress((void**)&pWpre, g_Wpre);
    cudaGetSymbolAddress((void**)&pWt,  g_Wt);

    // dynamic smem: 2 buffers of (A pair + B single), ROWB=80
    const int SMEM_128 = 2 * (2 * 128 * 80 + 128 * 80);   // 61440
    const int SMEM_64  = 2 * (2 * 64 * 80 + 128 * 80);    // 40960
    cudaFuncSetAttribute((const void*)gemm_mma<128, 128, 64, 64, 0>,
                         cudaFuncAttributeMaxDynamicSharedMemorySize, SMEM_128);
    cudaFuncSetAttribute((const void*)gemm_mma<64, 128, 32, 64, 2>,
                         cudaFuncAttributeMaxDynamicSharedMemorySize, SMEM_64);
    cudaFuncSetAttribute((const void*)gemm_mma<128, 128, 64, 64, 1>,
                         cudaFuncAttributeMaxDynamicSharedMemorySize, SMEM_128);

    prep_tables<<<1024, 256>>>(f2, f3);
    prep_x<<<32768, 256>>>(x);

    // stage 1: G[ij][ce][bd] fp16 single
    pair01_kernel<<<1024, 256>>>(f0, f1);

    // stage 2: per-ij H[kf=1024][ce=256] = (F2h+F2l) . G_ij^T   (K=256)
    gemm_mma<128, 128, 64, 64, 0><<<dim3(2, 8, 1024), 128, SMEM_128>>>(
        pF2h, pF2l, pG,
        nullptr, pH, nullptr,
        /*K=*/256, /*lda=*/256, /*ldb=*/256, /*ldC=*/256,
        /*sB=*/65536LL, /*sC=*/262144LL);

    // stage 3: Wpre[l=64][(ij,k)=65536] = (F3h+F3l) . H^T       (K=4096)
    gemm_mma<64, 128, 32, 64, 2><<<dim3(512, 1, 1), 128, SMEM_64>>>(
        pF3h, pF3l, pH,
        pWpre, nullptr, nullptr,
        /*K=*/4096, /*lda=*/4096, /*ldb=*/4096, /*ldC=*/65536,
        /*sB=*/0, /*sC=*/0);

    // transpose -> Wt[(k,l)][ij] fp16 single
    wtrans_kernel<<<4096, 256>>>();

    // stage 4: out[8192][4096] = (xh+xl) . Wt^T + bias          (K=1024)
    gemm_mma<128, 128, 64, 64, 1><<<dim3(32, 64, 1), 128, SMEM_128>>>(
        pxh, pxl, pWt,
        out, nullptr, bias,
        /*K=*/1024, /*lda=*/1024, /*ldb=*/1024, /*ldC=*/4096,
        0, 0);
}

// round 12
// speedup vs baseline: 6.4337x; 1.5116x over previous
#include <cuda_runtime.h>
#include <cuda_fp16.h>
#include <cstdint>

// =====================================================================
// Tree (121 GMAC):
//  G[ij][ce][bd]    = sum_a f0[i,a,b,c] f1[a,j,d,e]      (fp32 -> fp16)
//  H[ij][kf][ce]    = F2[kf,bd] . G[ce,bd]^T             (1-MMA, batched)
//  Wpre[l][(ij,k)]  = F3[l,(f,ce)] . H[(ij,k),(f,ce)]^T  (1-MMA)
//  out[z][kl]       = x[z,ij] . Wt[kl,ij]^T + bias       (1-MMA)
//
// All operands single fp16, fp32 accumulate. 6 independent fp16 rounding
// sources => rel_err ~ 5e-4 < 1e-3 (measured 3.6e-4 with 3 sources in R11).
// Issued tensor FLOPs: 241 GFLOP at the measured ~320 TF/s mma.sync
// instruction ceiling (harness PTX target sm_100 => no tcgen05).
// =====================================================================

typedef __half fp16;

// ------------------- scratch (device globals) ------------------------
__device__ __align__(256) fp16  g_F2[1024 * 256];
__device__ __align__(256) fp16  g_F3[64 * 4096];
__device__ __align__(256) fp16  g_x[8192 * 1024];
__device__ __align__(256) fp16  g_G[1024LL * 256 * 256];     // 128 MB
__device__ __align__(256) fp16  g_H[1024LL * 1024 * 256];    // 512 MB
__device__ __align__(256) float g_Wpre[64LL * 65536];        // 16 MB
__device__ __align__(256) fp16  g_Wt[4096 * 1024];           // 8 MB

// ------------------- helpers ------------------------------------------
__device__ __forceinline__ uint32_t smem_u32(const void* p) {
    uint32_t a;
    asm("{ .reg .u64 t; cvta.to.shared.u64 t, %1; cvt.u32.u64 %0, t; }"
        : "=r"(a) : "l"(p));
    return a;
}
__device__ __forceinline__ void cp16(uint32_t s, const void* g) {
    asm volatile("cp.async.cg.shared.global [%0], [%1], 16;" :: "r"(s), "l"(g));
}
__device__ __forceinline__ void cp_commit() {
    asm volatile("cp.async.commit_group;" ::: "memory");
}
__device__ __forceinline__ void cp_wait0() {
    asm volatile("cp.async.wait_group 0;" ::: "memory");
}
__device__ __forceinline__ void ldsm4(uint32_t& r0, uint32_t& r1,
                                      uint32_t& r2, uint32_t& r3, uint32_t addr) {
    asm volatile("ldmatrix.sync.aligned.m8n8.x4.shared.b16 {%0,%1,%2,%3}, [%4];"
                 : "=r"(r0), "=r"(r1), "=r"(r2), "=r"(r3) : "r"(addr));
}
__device__ __forceinline__ void mma16816(float (&d)[4], const uint32_t (&a)[4],
                                         const uint32_t (&b)[2]) {
    asm volatile(
        "mma.sync.aligned.m16n8k16.row.col.f32.f16.f16.f32 "
        "{%0,%1,%2,%3}, {%4,%5,%6,%7}, {%8,%9}, {%0,%1,%2,%3};"
        : "+f"(d[0]), "+f"(d[1]), "+f"(d[2]), "+f"(d[3])
        : "r"(a[0]), "r"(a[1]), "r"(a[2]), "r"(a[3]), "r"(b[0]), "r"(b[1]));
}

// ------------------- prep: tables + x --------------------------------
__global__ void prep_tables(const float* __restrict__ f2,
                            const float* __restrict__ f3) {
    int o = blockIdx.x * 256 + threadIdx.x;          // 0 .. 262143
    // F2t[kf][bd] = f2[(bd)*1024 + kf]
    g_F2[o] = __float2half(f2[(o & 255) * 1024 + (o >> 8)]);
    // F3T[l][f*256 + c*16 + e] = f3[((c*16+e)*16+f)*64 + l]
    int l = o >> 12, fce = o & 4095, f = fce >> 8, ce = fce & 255;
    g_F3[o] = __float2half(f3[(ce * 16 + f) * 64 + l]);
}
__global__ void prep_x(const float* __restrict__ x) {
    int o = blockIdx.x * 256 + threadIdx.x;
    g_x[o] = __float2half(x[o]);
}

// ------------------- stage 1: G[ij][ce][bd] fp16 -----------------------
__global__ void __launch_bounds__(256)
pair01_kernel(const float* __restrict__ f0, const float* __restrict__ f1) {
    __shared__ float s0[4096];   // f0[i]: a*256 + b*16 + c
    __shared__ float s1[4096];   // f1[:,j]: a*256 + d*16 + e
    const int t = threadIdx.x, ij = blockIdx.x;
    const int i = ij >> 5, j = ij & 31;

    for (int p = t; p < 4096; p += 256) {
        s0[p] = f0[i * 4096 + p];
        int a = p >> 8, de = p & 255;
        s1[p] = f1[a * 8192 + j * 256 + de];
    }
    __syncthreads();

    const int c = t >> 4, e = t & 15;
    const long long ob = (long long)ij * 65536 + (long long)t * 256;  // row = ce

    for (int b = 0; b < 16; b++) {
        float r0[16];
        #pragma unroll
        for (int a = 0; a < 16; a++) r0[a] = s0[a * 256 + b * 16 + c];
        __align__(16) fp16 hv[16];
        #pragma unroll
        for (int d = 0; d < 16; d++) {
            float acc = 0.f;
            #pragma unroll
            for (int a = 0; a < 16; a++) acc += r0[a] * s1[a * 256 + d * 16 + e];
            hv[d] = __float2half(acc);
        }
        *reinterpret_cast<uint4*>(&g_G[ob + b * 16])     = reinterpret_cast<uint4*>(hv)[0];
        *reinterpret_cast<uint4*>(&g_G[ob + b * 16 + 8]) = reinterpret_cast<uint4*>(hv)[1];
    }
}

// ------------------- fp16 single GEMM ----------------------------------
// D[M,N] = A[M,K] * B[N,K]^T ; all K-major rows, lda/ldb leads.
// z-dim: B += z*sB, C += z*sC  (A has no batch).
// EPI: 0 -> fp16 out; 1 -> fp32 + bias; 2 -> fp32 plain.
template <int BM, int BN, int WM, int WN, int EPI>
__global__ void __launch_bounds__((BM / WM) * (BN / WN) * 32)
gemm_mma(const fp16* __restrict__ A, const fp16* __restrict__ B,
         float* __restrict__ Cf, fp16* __restrict__ Ch,
         const float* __restrict__ bias,
         int K, int lda, int ldb, int ldC,
         long long sB, long long sC) {
    constexpr int WARPS_M = BM / WM, WARPS_N = BN / WN;
    constexpr int THREADS = WARPS_M * WARPS_N * 32;
    constexpr int MT = WM / 16, NT = WN / 8;
    static_assert(NT % 2 == 0, "NT even for paired ldsm4");
    constexpr int ROWB = 80;                 // 64B data + 16B pad (bank-safe)
    constexpr int A_SZ = BM * ROWB;
    constexpr int B_SZ = BN * ROWB;
    constexpr int BUFB = A_SZ + B_SZ;

    extern __shared__ char sm[];
    const uint32_t sbase = smem_u32(sm);
    const int tid = threadIdx.x, wid = tid >> 5, lane = tid & 31;
    const int warp_m0 = (wid / WARPS_N) * WM;
    const int warp_n0 = (wid % WARPS_N) * WN;

    const long long bz = blockIdx.z;
    B += bz * sB;
    const int m0 = blockIdx.y * BM;
    const int n0 = blockIdx.x * BN;

    float acc[MT][NT][4];
    #pragma unroll
    for (int mi = 0; mi < MT; mi++)
        #pragma unroll
        for (int ni = 0; ni < NT; ni++)
            #pragma unroll
            for (int c = 0; c < 4; c++) acc[mi][ni][c] = 0.f;

    auto load_chunk = [&](int kt, int buf) {
        const uint32_t sA = sbase + buf * BUFB;
        const uint32_t sBb = sA + A_SZ;
        #pragma unroll
        for (int p = tid; p < BM * 4; p += THREADS) {
            int row = p >> 2, u = p & 3;
            long long g = (long long)(m0 + row) * lda + kt + u * 8;
            cp16(sA + row * ROWB + u * 16, A + g);
        }
        #pragma unroll
        for (int p = tid; p < BN * 4; p += THREADS) {
            int row = p >> 2, u = p & 3;
            long long g = (long long)(n0 + row) * ldb + kt + u * 8;
            cp16(sBb + row * ROWB + u * 16, B + g);
        }
        cp_commit();
    };

    const int nch = K >> 5;   // BK = 32
    load_chunk(0, 0);
    cp_wait0();
    __syncthreads();

    for (int t = 0; t < nch; t++) {
        const int buf = t & 1;
        if (t + 1 < nch) load_chunk((t + 1) * 32, buf ^ 1);

        const uint32_t sA = sbase + buf * BUFB;
        const uint32_t sBb = sA + A_SZ;

        #pragma unroll
        for (int ks = 0; ks < 2; ks++) {
            uint32_t af[MT][4], bq[NT][2];
            #pragma unroll
            for (int mi = 0; mi < MT; mi++) {
                uint32_t off = (uint32_t)(warp_m0 + mi * 16 + (lane & 15)) * ROWB +
                               ks * 32 + (lane >> 4) * 16;
                ldsm4(af[mi][0], af[mi][1], af[mi][2], af[mi][3], sA + off);
            }
            #pragma unroll
            for (int ni = 0; ni < NT; ni += 2) {
                uint32_t off = (uint32_t)(warp_n0 + ni * 8 + ((lane >> 4) << 3) +
                                          (lane & 7)) * ROWB +
                               ks * 32 + ((lane >> 3) & 1) * 16;
                ldsm4(bq[ni][0], bq[ni][1], bq[ni + 1][0], bq[ni + 1][1], sBb + off);
            }
            #pragma unroll
            for (int mi = 0; mi < MT; mi++)
                #pragma unroll
                for (int ni = 0; ni < NT; ni++)
                    mma16816(acc[mi][ni], af[mi], bq[ni]);
        }
        cp_wait0();
        __syncthreads();
    }

    // epilogue: thread holds (r, col),(r, col+1),(r+8, col),(r+8, col+1)
    #pragma unroll
    for (int mi = 0; mi < MT; mi++) {
        #pragma unroll
        for (int ni = 0; ni < NT; ni++) {
            int r   = m0 + warp_m0 + mi * 16 + (lane >> 2);
            int col = n0 + warp_n0 + ni * 8 + (lane & 3) * 2;
            if (EPI == 0) {
                #pragma unroll
                for (int half_ = 0; half_ < 2; half_++) {
                    long long off = bz * sC + (long long)(r + half_ * 8) * ldC + col;
                    __half2 hv;
                    hv.x = __float2half(acc[mi][ni][half_ * 2]);
                    hv.y = __float2half(acc[mi][ni][half_ * 2 + 1]);
                    *reinterpret_cast<__half2*>(&Ch[off]) = hv;
                }
            } else if (EPI == 1) {
                float b0 = bias[col], b1 = bias[col + 1];
                #pragma unroll
                for (int half_ = 0; half_ < 2; half_++) {
                    long long off = (long long)(r + half_ * 8) * ldC + col;
                    float2 v;
                    v.x = acc[mi][ni][half_ * 2]     + b0;
                    v.y = acc[mi][ni][half_ * 2 + 1] + b1;
                    *reinterpret_cast<float2*>(&Cf[off]) = v;
                }
            } else {
                #pragma unroll
                for (int half_ = 0; half_ < 2; half_++) {
                    long long off = (long long)(r + half_ * 8) * ldC + col;
                    float2 v;
                    v.x = acc[mi][ni][half_ * 2];
                    v.y = acc[mi][ni][half_ * 2 + 1];
                    *reinterpret_cast<float2*>(&Cf[off]) = v;
                }
            }
        }
    }
}

// -------- Wpre[l][(ij,k)] fp32 -> Wt[(k*64+l)][ij] fp16 ----------------
__global__ void __launch_bounds__(256)
wtrans_kernel() {
    const int kl = blockIdx.x;           // 0..4095
    const int k = kl >> 6, l = kl & 63;
    const int t = threadIdx.x;
    #pragma unroll
    for (int q = 0; q < 4; q++) {
        int ij = t + q * 256;
        float v = g_Wpre[(long long)l * 65536 + ij * 64 + k];
        g_Wt[(long long)kl * 1024 + ij] = __float2half(v);
    }
}

// ------------------- launch -------------------------------------------
extern "C" void kernel_launch(void* const* d_in, const int* in_sizes, int n_in,
                              void* d_out, int out_size) {
    const float* x    = (const float*)d_in[0];
    const float* f0   = (const float*)d_in[1];
    const float* f1   = (const float*)d_in[2];
    const float* f2   = (const float*)d_in[3];
    const float* f3   = (const float*)d_in[4];
    const float* bias = (const float*)d_in[5];
    float* out = (float*)d_out;

    fp16 *pF2, *pF3, *px, *pG, *pH, *pWt;
    float* pWpre;
    cudaGetSymbolAddress((void**)&pF2, g_F2);
    cudaGetSymbolAddress((void**)&pF3, g_F3);
    cudaGetSymbolAddress((void**)&px,  g_x);
    cudaGetSymbolAddress((void**)&pG,  g_G);
    cudaGetSymbolAddress((void**)&pH,  g_H);
    cudaGetSymbolAddress((void**)&pWpre, g_Wpre);
    cudaGetSymbolAddress((void**)&pWt, g_Wt);

    // dynamic smem: 2 buffers of (A + B), ROWB=80
    const int SMEM_128 = 2 * (128 * 80 + 128 * 80);   // 40960
    const int SMEM_64  = 2 * (64 * 80 + 128 * 80);    // 30720
    cudaFuncSetAttribute((const void*)gemm_mma<128, 128, 64, 64, 0>,
                         cudaFuncAttributeMaxDynamicSharedMemorySize, SMEM_128);
    cudaFuncSetAttribute((const void*)gemm_mma<64, 128, 32, 64, 2>,
                         cudaFuncAttributeMaxDynamicSharedMemorySize, SMEM_64);
    cudaFuncSetAttribute((const void*)gemm_mma<128, 128, 64, 64, 1>,
                         cudaFuncAttributeMaxDynamicSharedMemorySize, SMEM_128);

    prep_tables<<<1024, 256>>>(f2, f3);
    prep_x<<<32768, 256>>>(x);

    // stage 1: G[ij][ce][bd] fp16
    pair01_kernel<<<1024, 256>>>(f0, f1);

    // stage 2: per-ij H[kf=1024][ce=256] = F2 . G_ij^T   (K=256)
    gemm_mma<128, 128, 64, 64, 0><<<dim3(2, 8, 1024), 128, SMEM_128>>>(
        pF2, pG,
        nullptr, pH, nullptr,
        /*K=*/256, /*lda=*/256, /*ldb=*/256, /*ldC=*/256,
        /*sB=*/65536LL, /*sC=*/262144LL);

    // stage 3: Wpre[l=64][(ij,k)=65536] = F3 . H^T       (K=4096)
    gemm_mma<64, 128, 32, 64, 2><<<dim3(512, 1, 1), 128, SMEM_64>>>(
        pF3, pH,
        pWpre, nullptr, nullptr,
        /*K=*/4096, /*lda=*/4096, /*ldb=*/4096, /*ldC=*/65536,
        /*sB=*/0, /*sC=*/0);

    // transpose -> Wt[(k,l)][ij] fp16
    wtrans_kernel<<<4096, 256>>>();

    // stage 4: out[8192][4096] = x . Wt^T + bias         (K=1024)
    gemm_mma<128, 128, 64, 64, 1><<<dim3(32, 64, 1), 128, SMEM_128>>>(
        px, pWt,
        out, nullptr, bias,
        /*K=*/1024, /*lda=*/1024, /*ldb=*/1024, /*ldC=*/4096,
        0, 0);
}

// round 13
// speedup vs baseline: 6.6998x; 1.0414x over previous
#include <cuda_runtime.h>
#include <cuda_fp16.h>
#include <cstdint>

// =====================================================================
// Tree (121 GMAC):
//  G[ij][ce][bd]    = sum_a f0[i,a,b,c] f1[a,j,d,e]      (fp32 -> fp16)
//  H[ij][kf][ce]    = F2[kf,bd] . G[ce,bd]^T             (1-MMA, batched)
//  Wpre[l][(ij,k)]  = F3[l,(f,ce)] . H[(ij,k),(f,ce)]^T  (1-MMA)
//  out[z][kl]       = x[z,ij] . Wt[kl,ij]^T + bias       (1-MMA)
//
// All operands single fp16, fp32 accumulate (rel_err ~5e-4, measured).
// BK=64: 4 k16-steps (128 MMAs) per barrier pair to cut sync overhead —
// R12 showed stage-2 slid from MMA-bound (323 TF) to issue/barrier-bound
// (254 TF) when MMAs per chunk halved. Harness PTX target sm_100 => legacy
// mma.sync path, measured instruction ceiling ~320 TF/s.
// =====================================================================

typedef __half fp16;

// ------------------- scratch (device globals) ------------------------
__device__ __align__(256) fp16  g_F2[1024 * 256];
__device__ __align__(256) fp16  g_F3[64 * 4096];
__device__ __align__(256) fp16  g_x[8192 * 1024];
__device__ __align__(256) fp16  g_G[1024LL * 256 * 256];     // 128 MB
__device__ __align__(256) fp16  g_H[1024LL * 1024 * 256];    // 512 MB
__device__ __align__(256) float g_Wpre[64LL * 65536];        // 16 MB
__device__ __align__(256) fp16  g_Wt[4096 * 1024];           // 8 MB

// ------------------- helpers ------------------------------------------
__device__ __forceinline__ uint32_t smem_u32(const void* p) {
    uint32_t a;
    asm("{ .reg .u64 t; cvta.to.shared.u64 t, %1; cvt.u32.u64 %0, t; }"
        : "=r"(a) : "l"(p));
    return a;
}
__device__ __forceinline__ void cp16(uint32_t s, const void* g) {
    asm volatile("cp.async.cg.shared.global [%0], [%1], 16;" :: "r"(s), "l"(g));
}
__device__ __forceinline__ void cp_commit() {
    asm volatile("cp.async.commit_group;" ::: "memory");
}
__device__ __forceinline__ void cp_wait0() {
    asm volatile("cp.async.wait_group 0;" ::: "memory");
}
__device__ __forceinline__ void ldsm4(uint32_t& r0, uint32_t& r1,
                                      uint32_t& r2, uint32_t& r3, uint32_t addr) {
    asm volatile("ldmatrix.sync.aligned.m8n8.x4.shared.b16 {%0,%1,%2,%3}, [%4];"
                 : "=r"(r0), "=r"(r1), "=r"(r2), "=r"(r3) : "r"(addr));
}
__device__ __forceinline__ void mma16816(float (&d)[4], const uint32_t (&a)[4],
                                         const uint32_t (&b)[2]) {
    asm volatile(
        "mma.sync.aligned.m16n8k16.row.col.f32.f16.f16.f32 "
        "{%0,%1,%2,%3}, {%4,%5,%6,%7}, {%8,%9}, {%0,%1,%2,%3};"
        : "+f"(d[0]), "+f"(d[1]), "+f"(d[2]), "+f"(d[3])
        : "r"(a[0]), "r"(a[1]), "r"(a[2]), "r"(a[3]), "r"(b[0]), "r"(b[1]));
}

// ------------------- prep: tables + x --------------------------------
__global__ void prep_tables(const float* __restrict__ f2,
                            const float* __restrict__ f3) {
    int o = blockIdx.x * 256 + threadIdx.x;          // 0 .. 262143
    // F2t[kf][bd] = f2[(bd)*1024 + kf]
    g_F2[o] = __float2half(f2[(o & 255) * 1024 + (o >> 8)]);
    // F3T[l][f*256 + c*16 + e] = f3[((c*16+e)*16+f)*64 + l]
    int l = o >> 12, fce = o & 4095, f = fce >> 8, ce = fce & 255;
    g_F3[o] = __float2half(f3[(ce * 16 + f) * 64 + l]);
}
__global__ void prep_x(const float* __restrict__ x) {
    int o = blockIdx.x * 256 + threadIdx.x;
    g_x[o] = __float2half(x[o]);
}

// ------------------- stage 1: G[ij][ce][bd] fp16 -----------------------
__global__ void __launch_bounds__(256)
pair01_kernel(const float* __restrict__ f0, const float* __restrict__ f1) {
    __shared__ float s0[4096];   // f0[i]: a*256 + b*16 + c
    __shared__ float s1[4096];   // f1[:,j]: a*256 + d*16 + e
    const int t = threadIdx.x, ij = blockIdx.x;
    const int i = ij >> 5, j = ij & 31;

    for (int p = t; p < 4096; p += 256) {
        s0[p] = f0[i * 4096 + p];
        int a = p >> 8, de = p & 255;
        s1[p] = f1[a * 8192 + j * 256 + de];
    }
    __syncthreads();

    const int c = t >> 4, e = t & 15;
    const long long ob = (long long)ij * 65536 + (long long)t * 256;  // row = ce

    for (int b = 0; b < 16; b++) {
        float r0[16];
        #pragma unroll
        for (int a = 0; a < 16; a++) r0[a] = s0[a * 256 + b * 16 + c];
        __align__(16) fp16 hv[16];
        #pragma unroll
        for (int d = 0; d < 16; d++) {
            float acc = 0.f;
            #pragma unroll
            for (int a = 0; a < 16; a++) acc += r0[a] * s1[a * 256 + d * 16 + e];
            hv[d] = __float2half(acc);
        }
        *reinterpret_cast<uint4*>(&g_G[ob + b * 16])     = reinterpret_cast<uint4*>(hv)[0];
        *reinterpret_cast<uint4*>(&g_G[ob + b * 16 + 8]) = reinterpret_cast<uint4*>(hv)[1];
    }
}

// ------------------- fp16 single GEMM, BK=64 ---------------------------
// D[M,N] = A[M,K] * B[N,K]^T ; all K-major rows, lda/ldb leads.
// z-dim: B += z*sB, C += z*sC  (A has no batch).
// EPI: 0 -> fp16 out; 1 -> fp32 + bias; 2 -> fp32 plain.
template <int BM, int BN, int WM, int WN, int EPI>
__global__ void __launch_bounds__((BM / WM) * (BN / WN) * 32)
gemm_mma(const fp16* __restrict__ A, const fp16* __restrict__ B,
         float* __restrict__ Cf, fp16* __restrict__ Ch,
         const float* __restrict__ bias,
         int K, int lda, int ldb, int ldC,
         long long sB, long long sC) {
    constexpr int WARPS_M = BM / WM, WARPS_N = BN / WN;
    constexpr int THREADS = WARPS_M * WARPS_N * 32;
    constexpr int MT = WM / 16, NT = WN / 8;
    static_assert(NT % 2 == 0, "NT even for paired ldsm4");
    constexpr int ROWB = 144;                // 128B data + 16B pad (bank-safe)
    constexpr int A_SZ = BM * ROWB;
    constexpr int B_SZ = BN * ROWB;
    constexpr int BUFB = A_SZ + B_SZ;

    extern __shared__ char sm[];
    const uint32_t sbase = smem_u32(sm);
    const int tid = threadIdx.x, wid = tid >> 5, lane = tid & 31;
    const int warp_m0 = (wid / WARPS_N) * WM;
    const int warp_n0 = (wid % WARPS_N) * WN;

    const long long bz = blockIdx.z;
    B += bz * sB;
    const int m0 = blockIdx.y * BM;
    const int n0 = blockIdx.x * BN;

    float acc[MT][NT][4];
    #pragma unroll
    for (int mi = 0; mi < MT; mi++)
        #pragma unroll
        for (int ni = 0; ni < NT; ni++)
            #pragma unroll
            for (int c = 0; c < 4; c++) acc[mi][ni][c] = 0.f;

    auto load_chunk = [&](int kt, int buf) {
        const uint32_t sA = sbase + buf * BUFB;
        const uint32_t sBb = sA + A_SZ;
        #pragma unroll
        for (int p = tid; p < BM * 8; p += THREADS) {
            int row = p >> 3, u = p & 7;
            long long g = (long long)(m0 + row) * lda + kt + u * 8;
            cp16(sA + row * ROWB + u * 16, A + g);
        }
        #pragma unroll
        for (int p = tid; p < BN * 8; p += THREADS) {
            int row = p >> 3, u = p & 7;
            long long g = (long long)(n0 + row) * ldb + kt + u * 8;
            cp16(sBb + row * ROWB + u * 16, B + g);
        }
        cp_commit();
    };

    const int nch = K >> 6;   // BK = 64
    load_chunk(0, 0);
    cp_wait0();
    __syncthreads();

    for (int t = 0; t < nch; t++) {
        const int buf = t & 1;
        if (t + 1 < nch) load_chunk((t + 1) * 64, buf ^ 1);

        const uint32_t sA = sbase + buf * BUFB;
        const uint32_t sBb = sA + A_SZ;

        #pragma unroll
        for (int ks = 0; ks < 4; ks++) {
            uint32_t af[MT][4], bq[NT][2];
            #pragma unroll
            for (int mi = 0; mi < MT; mi++) {
                uint32_t off = (uint32_t)(warp_m0 + mi * 16 + (lane & 15)) * ROWB +
                               ks * 32 + (lane >> 4) * 16;
                ldsm4(af[mi][0], af[mi][1], af[mi][2], af[mi][3], sA + off);
            }
            #pragma unroll
            for (int ni = 0; ni < NT; ni += 2) {
                uint32_t off = (uint32_t)(warp_n0 + ni * 8 + ((lane >> 4) << 3) +
                                          (lane & 7)) * ROWB +
                               ks * 32 + ((lane >> 3) & 1) * 16;
                ldsm4(bq[ni][0], bq[ni][1], bq[ni + 1][0], bq[ni + 1][1], sBb + off);
            }
            #pragma unroll
            for (int mi = 0; mi < MT; mi++)
                #pragma unroll
                for (int ni = 0; ni < NT; ni++)
                    mma16816(acc[mi][ni], af[mi], bq[ni]);
        }
        cp_wait0();
        __syncthreads();
    }

    // epilogue: thread holds (r, col),(r, col+1),(r+8, col),(r+8, col+1)
    #pragma unroll
    for (int mi = 0; mi < MT; mi++) {
        #pragma unroll
        for (int ni = 0; ni < NT; ni++) {
            int r   = m0 + warp_m0 + mi * 16 + (lane >> 2);
            int col = n0 + warp_n0 + ni * 8 + (lane & 3) * 2;
            if (EPI == 0) {
                #pragma unroll
                for (int half_ = 0; half_ < 2; half_++) {
                    long long off = bz * sC + (long long)(r + half_ * 8) * ldC + col;
                    __half2 hv;
                    hv.x = __float2half(acc[mi][ni][half_ * 2]);
                    hv.y = __float2half(acc[mi][ni][half_ * 2 + 1]);
                    *reinterpret_cast<__half2*>(&Ch[off]) = hv;
                }
            } else if (EPI == 1) {
                float b0 = bias[col], b1 = bias[col + 1];
                #pragma unroll
                for (int half_ = 0; half_ < 2; half_++) {
                    long long off = (long long)(r + half_ * 8) * ldC + col;
                    float2 v;
                    v.x = acc[mi][ni][half_ * 2]     + b0;
                    v.y = acc[mi][ni][half_ * 2 + 1] + b1;
                    *reinterpret_cast<float2*>(&Cf[off]) = v;
                }
            } else {
                #pragma unroll
                for (int half_ = 0; half_ < 2; half_++) {
                    long long off = (long long)(r + half_ * 8) * ldC + col;
                    float2 v;
                    v.x = acc[mi][ni][half_ * 2];
                    v.y = acc[mi][ni][half_ * 2 + 1];
                    *reinterpret_cast<float2*>(&Cf[off]) = v;
                }
            }
        }
    }
}

// -------- Wpre[l][(ij,k)] fp32 -> Wt[(k*64+l)][ij] fp16 ----------------
__global__ void __launch_bounds__(256)
wtrans_kernel() {
    const int kl = blockIdx.x;           // 0..4095
    const int k = kl >> 6, l = kl & 63;
    const int t = threadIdx.x;
    #pragma unroll
    for (int q = 0; q < 4; q++) {
        int ij = t + q * 256;
        float v = g_Wpre[(long long)l * 65536 + ij * 64 + k];
        g_Wt[(long long)kl * 1024 + ij] = __float2half(v);
    }
}

// ------------------- launch -------------------------------------------
extern "C" void kernel_launch(void* const* d_in, const int* in_sizes, int n_in,
                              void* d_out, int out_size) {
    const float* x    = (const float*)d_in[0];
    const float* f0   = (const float*)d_in[1];
    const float* f1   = (const float*)d_in[2];
    const float* f2   = (const float*)d_in[3];
    const float* f3   = (const float*)d_in[4];
    const float* bias = (const float*)d_in[5];
    float* out = (float*)d_out;

    fp16 *pF2, *pF3, *px, *pG, *pH, *pWt;
    float* pWpre;
    cudaGetSymbolAddress((void**)&pF2, g_F2);
    cudaGetSymbolAddress((void**)&pF3, g_F3);
    cudaGetSymbolAddress((void**)&px,  g_x);
    cudaGetSymbolAddress((void**)&pG,  g_G);
    cudaGetSymbolAddress((void**)&pH,  g_H);
    cudaGetSymbolAddress((void**)&pWpre, g_Wpre);
    cudaGetSymbolAddress((void**)&pWt, g_Wt);

    // dynamic smem: 2 buffers of (A + B), ROWB=144 (BK=64)
    const int SMEM_128 = 2 * (128 * 144 + 128 * 144);   // 73728
    const int SMEM_64  = 2 * (64 * 144 + 128 * 144);    // 55296
    cudaFuncSetAttribute((const void*)gemm_mma<128, 128, 64, 64, 0>,
                         cudaFuncAttributeMaxDynamicSharedMemorySize, SMEM_128);
    cudaFuncSetAttribute((const void*)gemm_mma<64, 128, 32, 64, 2>,
                         cudaFuncAttributeMaxDynamicSharedMemorySize, SMEM_64);
    cudaFuncSetAttribute((const void*)gemm_mma<128, 128, 64, 64, 1>,
                         cudaFuncAttributeMaxDynamicSharedMemorySize, SMEM_128);

    prep_tables<<<1024, 256>>>(f2, f3);
    prep_x<<<32768, 256>>>(x);

    // stage 1: G[ij][ce][bd] fp16
    pair01_kernel<<<1024, 256>>>(f0, f1);

    // stage 2: per-ij H[kf=1024][ce=256] = F2 . G_ij^T   (K=256)
    gemm_mma<128, 128, 64, 64, 0><<<dim3(2, 8, 1024), 128, SMEM_128>>>(
        pF2, pG,
        nullptr, pH, nullptr,
        /*K=*/256, /*lda=*/256, /*ldb=*/256, /*ldC=*/256,
        /*sB=*/65536LL, /*sC=*/262144LL);

    // stage 3: Wpre[l=64][(ij,k)=65536] = F3 . H^T       (K=4096)
    gemm_mma<64, 128, 32, 64, 2><<<dim3(512, 1, 1), 128, SMEM_64>>>(
        pF3, pH,
        pWpre, nullptr, nullptr,
        /*K=*/4096, /*lda=*/4096, /*ldb=*/4096, /*ldC=*/65536,
        /*sB=*/0, /*sC=*/0);

    // transpose -> Wt[(k,l)][ij] fp16
    wtrans_kernel<<<4096, 256>>>();

    // stage 4: out[8192][4096] = x . Wt^T + bias         (K=1024)
    gemm_mma<128, 128, 64, 64, 1><<<dim3(32, 64, 1), 128, SMEM_128>>>(
        px, pWt,
        out, nullptr, bias,
        /*K=*/1024, /*lda=*/1024, /*ldb=*/1024, /*ldC=*/4096,
        0, 0);
}